// round 13
// baseline (speedup 1.0000x reference)
#include <cuda_runtime.h>
#include <cuda_fp16.h>
#include <math.h>
#include <stdint.h>

#define D_MODEL 1024
#define D_FF    4096
#define SEQ     2048
#define BATCH   2
#define NTOK    (BATCH*SEQ)   // 4096
#define NHEAD   16
#define HDIM    64

// ---------------- scratch (device globals; no allocation allowed) ----------
__device__ __half g_qh  [NTOK * D_MODEL];
__device__ __half g_kh  [NTOK * D_MODEL];
__device__ __half g_vh  [NTOK * D_MODEL];
__device__ __half g_ctxh[NTOK * D_MODEL];
__device__ __half g_t1h [NTOK * D_MODEL];
__device__ __half g_hh  [NTOK * D_MODEL];
__device__ __half g_ffh [NTOK * D_FF];
// half copies of inputs/weights
__device__ __half g_xh  [NTOK * D_MODEL];
__device__ __half g_wqh [D_MODEL * D_MODEL];
__device__ __half g_wkh [D_MODEL * D_MODEL];
__device__ __half g_wvh [D_MODEL * D_MODEL];
__device__ __half g_woh [D_MODEL * D_MODEL];
__device__ __half g_ff1h[D_MODEL * D_FF];
__device__ __half g_ff2h[D_FF * D_MODEL];

// ---------------------------------------------------------------------------
__device__ __forceinline__ void cp_async16(void* smem_dst, const void* gmem_src) {
    uint32_t da = (uint32_t)__cvta_generic_to_shared(smem_dst);
    asm volatile("cp.async.cg.shared.global [%0], [%1], 16;\n" :: "r"(da), "l"(gmem_src));
}
__device__ __forceinline__ void cp_commit() {
    asm volatile("cp.async.commit_group;\n");
}
__device__ __forceinline__ void cp_wait1() {
    asm volatile("cp.async.wait_group 1;\n");
}
__device__ __forceinline__ void mma_f16(float* c, const uint32_t* a,
                                        uint32_t b0, uint32_t b1) {
    asm volatile(
        "mma.sync.aligned.m16n8k16.row.col.f32.f16.f16.f32 "
        "{%0,%1,%2,%3}, {%4,%5,%6,%7}, {%8,%9}, {%0,%1,%2,%3};"
        : "+f"(c[0]), "+f"(c[1]), "+f"(c[2]), "+f"(c[3])
        : "r"(a[0]), "r"(a[1]), "r"(a[2]), "r"(a[3]), "r"(b0), "r"(b1));
}
#define LDSM_X4(r0, r1, r2, r3, addr) \
    asm volatile("ldmatrix.sync.aligned.m8n8.x4.shared.b16 {%0,%1,%2,%3}, [%4];" \
        : "=r"(r0), "=r"(r1), "=r"(r2), "=r"(r3) : "r"(addr))
#define LDSM_X4T(r0, r1, r2, r3, addr) \
    asm volatile("ldmatrix.sync.aligned.m8n8.x4.trans.shared.b16 {%0,%1,%2,%3}, [%4];" \
        : "=r"(r0), "=r"(r1), "=r"(r2), "=r"(r3) : "r"(addr))

// fast exp2 on the FMA pipe (x <= 0), rel err ~2e-6
__device__ __forceinline__ float exp2p(float x) {
    x = fmaxf(x, -126.0f);
    float z = x + 12582912.0f;
    float f = x - (z - 12582912.0f);
    float p =            1.3333558146e-3f;
    p = fmaf(p, f, 9.6181291918e-3f);
    p = fmaf(p, f, 5.5504108664e-2f);
    p = fmaf(p, f, 2.4022650695e-1f);
    p = fmaf(p, f, 6.9314718056e-1f);
    p = fmaf(p, f, 1.0f);
    return __int_as_float((__float_as_int(z) << 23) + __float_as_int(p));
}

// ===========================================================================
// Prepass: convert x + 6 weight tensors fp32 -> fp16, 2 float4 per thread
// (independent load pairs -> MLP=2, hides DRAM latency).
// ===========================================================================
#define R_N0 (NTOK * D_MODEL / 4)
#define R_N1 (D_MODEL * D_MODEL / 4)
#define R_N2 (D_MODEL * D_FF / 4)
#define R_TOTAL (R_N0 + 4 * R_N1 + 2 * R_N2)
#define R_THREADS ((R_TOTAL + 1) / 2)

__device__ __forceinline__ void conv_map(int i, const float4* x, __half* xh,
    const float4* wq, __half* wqh, const float4* wk, __half* wkh,
    const float4* wv, __half* wvh, const float4* wo, __half* woh,
    const float4* f1, __half* f1h, const float4* f2, __half* f2h,
    const float4*& s, __half*& d, int& j)
{
    int off;
    if      (i < R_N0)                 { s = x;  d = xh;  off = 0; }
    else if (i < R_N0 + R_N1)          { s = wq; d = wqh; off = R_N0; }
    else if (i < R_N0 + 2*R_N1)        { s = wk; d = wkh; off = R_N0 + R_N1; }
    else if (i < R_N0 + 3*R_N1)        { s = wv; d = wvh; off = R_N0 + 2*R_N1; }
    else if (i < R_N0 + 4*R_N1)        { s = wo; d = woh; off = R_N0 + 3*R_N1; }
    else if (i < R_N0 + 4*R_N1 + R_N2) { s = f1; d = f1h; off = R_N0 + 4*R_N1; }
    else                               { s = f2; d = f2h; off = R_N0 + 4*R_N1 + R_N2; }
    j = i - off;
}

__global__ void __launch_bounds__(256) conv_all_kernel(
    const float4* __restrict__ x,   __half* __restrict__ xh,
    const float4* __restrict__ wq,  __half* __restrict__ wqh,
    const float4* __restrict__ wk,  __half* __restrict__ wkh,
    const float4* __restrict__ wv,  __half* __restrict__ wvh,
    const float4* __restrict__ wo,  __half* __restrict__ woh,
    const float4* __restrict__ f1,  __half* __restrict__ f1h,
    const float4* __restrict__ f2,  __half* __restrict__ f2h)
{
    int t = blockIdx.x * 256 + threadIdx.x;
    int i0 = t;
    int i1 = t + R_THREADS;

    const float4 *s0 = nullptr, *s1 = nullptr;
    __half *d0 = nullptr, *d1 = nullptr;
    int j0 = 0, j1 = 0;
    bool v0 = (i0 < R_TOTAL), v1 = (i1 < R_TOTAL);
    if (v0) conv_map(i0, x, xh, wq, wqh, wk, wkh, wv, wvh, wo, woh, f1, f1h, f2, f2h, s0, d0, j0);
    if (v1) conv_map(i1, x, xh, wq, wqh, wk, wkh, wv, wvh, wo, woh, f1, f1h, f2, f2h, s1, d1, j1);

    float4 a, b;
    if (v0) a = s0[j0];
    if (v1) b = s1[j1];

    if (v0) {
        __half2 h0 = __floats2half2_rn(a.x, a.y);
        __half2 h1 = __floats2half2_rn(a.z, a.w);
        uint2 pk;
        pk.x = *(uint32_t*)&h0;
        pk.y = *(uint32_t*)&h1;
        *(uint2*)(d0 + (size_t)j0 * 4) = pk;
    }
    if (v1) {
        __half2 h0 = __floats2half2_rn(b.x, b.y);
        __half2 h1 = __floats2half2_rn(b.z, b.w);
        uint2 pk;
        pk.x = *(uint32_t*)&h0;
        pk.y = *(uint32_t*)&h1;
        *(uint2*)(d1 + (size_t)j1 * 4) = pk;
    }
}

// ===========================================================================
// fp16 tensor-core GEMM (R8 config — mainloop byte-identical).
// CTA 128x128, BK=64, 3-stage cp.async, 4 warps (2x2), warp tile 64x64.
// ===========================================================================
#define GA_BYTES 16384
#define GB_PITCH 272
#define GB_BYTES (64 * GB_PITCH)
#define G_STAGE  (GA_BYTES + GB_BYTES)
#define G_SMEM   (3 * G_STAGE)
#define G_THREADS 128

template <bool RELU>
__device__ __forceinline__ void gemm_h_body(
    const __half* __restrict__ A, const __half* __restrict__ W,
    const float* __restrict__ bias, __half* __restrict__ Cout,
    int K, int M, int row0, int col0, float oscale)
{
    extern __shared__ char smem[];
    const int tid  = threadIdx.x;
    const int lane = tid & 31;
    const int wid  = tid >> 5;
    const int warp_m = wid & 1;
    const int warp_n = wid >> 1;
    const uint32_t sbase = (uint32_t)__cvta_generic_to_shared(smem);

    float acc[4][8][4];
#pragma unroll
    for (int mt = 0; mt < 4; mt++)
#pragma unroll
        for (int nt = 0; nt < 8; nt++)
#pragma unroll
            for (int r = 0; r < 4; r++) acc[mt][nt][r] = 0.0f;

    const int KT = K / 64;

    auto load_stage = [&](int kt) {
        char* base = smem + (kt % 3) * G_STAGE;
        const int k0 = kt * 64;
#pragma unroll
        for (int i = 0; i < 8; i++) {
            int c = tid + G_THREADS * i;
            int r = c >> 3, u = c & 7;
            cp_async16(base + r * 128 + (((u ^ (r & 7))) << 4),
                       A + (size_t)(row0 + r) * K + k0 + u * 8);
        }
#pragma unroll
        for (int i = 0; i < 8; i++) {
            int c = tid + G_THREADS * i;
            int k = c >> 4, u = c & 15;
            cp_async16(base + GA_BYTES + k * GB_PITCH + u * 16,
                       W + (size_t)(k0 + k) * M + col0 + u * 8);
        }
        cp_commit();
    };

    load_stage(0);
    load_stage(1);

    for (int kt = 0; kt < KT; kt++) {
        cp_wait1();
        __syncthreads();
        if (kt + 2 < KT) load_stage(kt + 2);
        else cp_commit();

        const uint32_t ab = sbase + (uint32_t)((kt % 3) * G_STAGE);
        const uint32_t bb = ab + GA_BYTES;

#pragma unroll
        for (int k16 = 0; k16 < 4; k16++) {
            uint32_t a[4][4];
#pragma unroll
            for (int mt = 0; mt < 4; mt++) {
                int m = warp_m * 64 + mt * 16 + (lane & 7) + ((lane >> 3) & 1) * 8;
                int u = k16 * 2 + (lane >> 4);
                LDSM_X4(a[mt][0], a[mt][1], a[mt][2], a[mt][3],
                        ab + m * 128 + ((u ^ (m & 7)) << 4));
            }
            uint32_t b[8][2];
#pragma unroll
            for (int ng = 0; ng < 4; ng++) {
                int k    = k16 * 16 + (lane & 7) + ((lane >> 3) & 1) * 8;
                int noff = warp_n * 64 + ng * 16 + ((lane >> 4) & 1) * 8;
                LDSM_X4T(b[ng*2][0], b[ng*2][1], b[ng*2+1][0], b[ng*2+1][1],
                         bb + k * GB_PITCH + noff * 2);
            }
#pragma unroll
            for (int mt = 0; mt < 4; mt++)
#pragma unroll
                for (int nt = 0; nt < 8; nt++)
                    mma_f16(acc[mt][nt], a[mt], b[nt][0], b[nt][1]);
        }
        __syncthreads();
    }

    // ---- epilogue: bias (+ReLU), half2 stores ----
#pragma unroll
    for (int nt = 0; nt < 8; nt++) {
        int ncol = col0 + warp_n * 64 + nt * 8 + (lane & 3) * 2;
        float bj0 = bias[ncol];
        float bj1 = bias[ncol + 1];
#pragma unroll
        for (int mt = 0; mt < 4; mt++) {
            int r0 = row0 + warp_m * 64 + mt * 16 + (lane >> 2);
            float v0 = (acc[mt][nt][0] + bj0) * oscale;
            float v1 = (acc[mt][nt][1] + bj1) * oscale;
            float v2 = (acc[mt][nt][2] + bj0) * oscale;
            float v3 = (acc[mt][nt][3] + bj1) * oscale;
            if (RELU) {
                v0 = fmaxf(v0, 0.0f); v1 = fmaxf(v1, 0.0f);
                v2 = fmaxf(v2, 0.0f); v3 = fmaxf(v3, 0.0f);
            }
            __half2 h0 = __floats2half2_rn(v0, v1);
            __half2 h1 = __floats2half2_rn(v2, v3);
            *(__half2*)(Cout + (size_t)r0 * M + ncol)       = h0;
            *(__half2*)(Cout + (size_t)(r0 + 8) * M + ncol) = h1;
        }
    }
}

template <bool RELU>
__global__ void __launch_bounds__(G_THREADS) gemm_h_kernel(
    const __half* __restrict__ A, const __half* __restrict__ W,
    const float* __restrict__ bias, __half* __restrict__ Cout, int K, int M)
{
    gemm_h_body<RELU>(A, W, bias, Cout, K, M,
                      blockIdx.y * 128, blockIdx.x * 128, 1.0f);
}

#define QSCALE (0.125f * 1.4426950408889634f)   // 1/sqrt(64) * log2(e)

__global__ void __launch_bounds__(G_THREADS) qkv_h_kernel(
    const __half* __restrict__ x,
    const __half* __restrict__ wq, const float* __restrict__ bq,
    const __half* __restrict__ wk, const float* __restrict__ bk,
    const __half* __restrict__ wv, const float* __restrict__ bv,
    __half* __restrict__ q, __half* __restrict__ k, __half* __restrict__ v,
    int K, int M)
{
    const int z = blockIdx.z;
    const __half* W    = (z == 0) ? wq : (z == 1) ? wk : wv;
    const float*  bias = (z == 0) ? bq : (z == 1) ? bk : bv;
    __half*       C    = (z == 0) ? q  : (z == 1) ? k  : v;
    float oscale = (z == 0) ? QSCALE : 1.0f;
    gemm_h_body<false>(x, W, bias, C, K, M,
                       blockIdx.y * 128, blockIdx.x * 128, oscale);
}

// ===========================================================================
// Flash attention, fp16 mma (f32 acc), KV tile = 128 (R8 — best measured).
// ===========================================================================
#define AK_PITCH 144
#define AK_BYTES (128 * AK_PITCH)
#define AV_OFF   (2 * AK_BYTES)
#define AP_OFF   (4 * AK_BYTES)
#define ATT_SMEM (AP_OFF + 128 * 256)

__global__ void __launch_bounds__(256, 1) attention_h_kernel(
    const __half* __restrict__ Q, const __half* __restrict__ K,
    const __half* __restrict__ V, __half* __restrict__ O)
{
    extern __shared__ char smem[];
    const uint32_t sbase = (uint32_t)__cvta_generic_to_shared(smem);

    const int tid  = threadIdx.x;
    const int lane = tid & 31;
    const int wid  = tid >> 5;
    const int b    = blockIdx.y >> 4;
    const int h    = blockIdx.y & 15;
    const int qr   = blockIdx.x * 128 + wid * 16;

    const __half* Qb = Q + ((size_t)(b * SEQ + qr)) * D_MODEL + h * HDIM;
    const __half* Kb = K + ((size_t)(b * SEQ)) * D_MODEL + h * HDIM;
    const __half* Vb = V + ((size_t)(b * SEQ)) * D_MODEL + h * HDIM;

    uint32_t qf[4][4];
    {
        const int r = lane >> 2, c2 = (lane & 3) * 2;
#pragma unroll
        for (int k16 = 0; k16 < 4; k16++) {
            qf[k16][0] = *(const uint32_t*)(Qb + (size_t)r * D_MODEL + k16 * 16 + c2);
            qf[k16][1] = *(const uint32_t*)(Qb + (size_t)(r + 8) * D_MODEL + k16 * 16 + c2);
            qf[k16][2] = *(const uint32_t*)(Qb + (size_t)r * D_MODEL + k16 * 16 + c2 + 8);
            qf[k16][3] = *(const uint32_t*)(Qb + (size_t)(r + 8) * D_MODEL + k16 * 16 + c2 + 8);
        }
    }

    auto load_kv = [&](int kt, int st) {
        const __half* Kt = Kb + (size_t)kt * 128 * D_MODEL;
        const __half* Vt = Vb + (size_t)kt * 128 * D_MODEL;
        char* kd = smem + st * AK_BYTES;
        char* vd = smem + AV_OFF + st * AK_BYTES;
#pragma unroll
        for (int i = 0; i < 4; i++) {
            int c = tid + 256 * i;
            int r = c >> 3, u = c & 7;
            cp_async16(kd + r * AK_PITCH + u * 16, Kt + (size_t)r * D_MODEL + u * 8);
            cp_async16(vd + r * AK_PITCH + u * 16, Vt + (size_t)r * D_MODEL + u * 8);
        }
        cp_commit();
    };

    float m0 = -1e30f, m1 = -1e30f, l0 = 0.0f, l1 = 0.0f;
    float oacc[8][4];
#pragma unroll
    for (int dt = 0; dt < 8; dt++)
#pragma unroll
        for (int r = 0; r < 4; r++) oacc[dt][r] = 0.0f;

    load_kv(0, 0);
    load_kv(1, 1);
    cp_wait1();
    __syncthreads();

    const int NKT = SEQ / 128;   // 16
    for (int kt = 0; kt < NKT; kt++) {
        const __half* kd = (const __half*)(smem + (kt & 1) * AK_BYTES);
        const uint32_t vdb = sbase + (uint32_t)(AV_OFF + (kt & 1) * AK_BYTES);

        float sacc[16][4];
#pragma unroll
        for (int nt = 0; nt < 16; nt++) {
            sacc[nt][0] = 0.0f; sacc[nt][1] = 0.0f;
            sacc[nt][2] = 0.0f; sacc[nt][3] = 0.0f;
            const int j = nt * 8 + (lane >> 2);
#pragma unroll
            for (int k16 = 0; k16 < 4; k16++) {
                int idx = j * 72 + k16 * 16 + (lane & 3) * 2;
                uint32_t b0 = *(const uint32_t*)(kd + idx);
                uint32_t b1 = *(const uint32_t*)(kd + idx + 8);
                mma_f16(sacc[nt], qf[k16], b0, b1);
            }
        }

        float mx0 = -1e30f, mx1 = -1e30f;
#pragma unroll
        for (int nt = 0; nt < 16; nt++) {
            mx0 = fmaxf(mx0, fmaxf(sacc[nt][0], sacc[nt][1]));
            mx1 = fmaxf(mx1, fmaxf(sacc[nt][2], sacc[nt][3]));
        }
        mx0 = fmaxf(mx0, __shfl_xor_sync(0xffffffffu, mx0, 1));
        mx0 = fmaxf(mx0, __shfl_xor_sync(0xffffffffu, mx0, 2));
        mx1 = fmaxf(mx1, __shfl_xor_sync(0xffffffffu, mx1, 1));
        mx1 = fmaxf(mx1, __shfl_xor_sync(0xffffffffu, mx1, 2));
        float mn0 = fmaxf(m0, mx0), mn1 = fmaxf(m1, mx1);
        float sc0 = exp2p(m0 - mn0), sc1 = exp2p(m1 - mn1);
        m0 = mn0; m1 = mn1;

        const int prow = wid * 16 + (lane >> 2);
        char* Pb = smem + AP_OFF;
        float rs0 = 0.0f, rs1 = 0.0f;
#pragma unroll
        for (int nt = 0; nt < 16; nt++) {
            float p0 = exp2p(sacc[nt][0] - mn0);
            float p1 = exp2p(sacc[nt][1] - mn0);
            float p2 = exp2p(sacc[nt][2] - mn1);
            float p3 = exp2p(sacc[nt][3] - mn1);
            rs0 += p0 + p1;
            rs1 += p2 + p3;
            __half2 hp0 = __floats2half2_rn(p0, p1);
            __half2 hp1 = __floats2half2_rn(p2, p3);
            int bo = ((nt ^ (prow & 7)) << 4) + (lane & 3) * 4;
            *(__half2*)(Pb + prow * 256 + bo)       = hp0;
            *(__half2*)(Pb + (prow + 8) * 256 + bo) = hp1;
        }
        rs0 += __shfl_xor_sync(0xffffffffu, rs0, 1);
        rs0 += __shfl_xor_sync(0xffffffffu, rs0, 2);
        rs1 += __shfl_xor_sync(0xffffffffu, rs1, 1);
        rs1 += __shfl_xor_sync(0xffffffffu, rs1, 2);
        l0 = l0 * sc0 + rs0;
        l1 = l1 * sc1 + rs1;
#pragma unroll
        for (int dt = 0; dt < 8; dt++) {
            oacc[dt][0] *= sc0; oacc[dt][1] *= sc0;
            oacc[dt][2] *= sc1; oacc[dt][3] *= sc1;
        }
        __syncwarp();

        const uint32_t pbb = sbase + AP_OFF;
#pragma unroll
        for (int k16 = 0; k16 < 8; k16++) {
            uint32_t pf[4];
            {
                int row = wid * 16 + (lane & 7) + ((lane >> 3) & 1) * 8;
                int u   = k16 * 2 + (lane >> 4);
                LDSM_X4(pf[0], pf[1], pf[2], pf[3],
                        pbb + row * 256 + ((u ^ (row & 7)) << 4));
            }
            uint32_t vb[8][2];
#pragma unroll
            for (int ng = 0; ng < 4; ng++) {
                int j    = k16 * 16 + (lane & 7) + ((lane >> 3) & 1) * 8;
                int doff = ng * 16 + ((lane >> 4) & 1) * 8;
                LDSM_X4T(vb[ng*2][0], vb[ng*2][1], vb[ng*2+1][0], vb[ng*2+1][1],
                         vdb + j * AK_PITCH + doff * 2);
            }
#pragma unroll
            for (int dt = 0; dt < 8; dt++)
                mma_f16(oacc[dt], pf, vb[dt][0], vb[dt][1]);
        }

        __syncthreads();
        if (kt + 2 < NKT) load_kv(kt + 2, kt & 1);
        else cp_commit();
        cp_wait1();
        __syncthreads();
    }

    float inv0 = 1.0f / l0, inv1 = 1.0f / l1;
    const size_t row0 = (size_t)(b * SEQ + qr + (lane >> 2));
#pragma unroll
    for (int dt = 0; dt < 8; dt++) {
        int col = h * HDIM + dt * 8 + 2 * (lane & 3);
        __half2 h0 = __floats2half2_rn(oacc[dt][0] * inv0, oacc[dt][1] * inv0);
        __half2 h1 = __floats2half2_rn(oacc[dt][2] * inv1, oacc[dt][3] * inv1);
        *(__half2*)(O + row0 * D_MODEL + col)       = h0;
        *(__half2*)(O + (row0 + 8) * D_MODEL + col) = h1;
    }
}

// ---------------------------------------------------------------------------
// Fused residual add + LayerNorm. A: fp32 (x) or half (hh). R: half (t1h).
// Outputs: fp32 `out` (may be null), half `out_h` (may be null).
// ---------------------------------------------------------------------------
template <bool AHALF>
__global__ void __launch_bounds__(256) add_ln_kernel(
    const void* __restrict__ Ain, const __half* __restrict__ R,
    const float* __restrict__ g, const float* __restrict__ beta,
    float* __restrict__ out, __half* __restrict__ out_h)
{
    const int row = blockIdx.x;
    const int t   = threadIdx.x;

    float a0, a1, a2, a3;
    if (AHALF) {
        const __half* Ah = (const __half*)Ain;
        uint2 pk = *(const uint2*)(Ah + (size_t)row * D_MODEL + t * 4);
        float2 f0 = __half22float2(*(__half2*)&pk.x);
        float2 f1 = __half22float2(*(__half2*)&pk.y);
        a0 = f0.x; a1 = f0.y; a2 = f1.x; a3 = f1.y;
    } else {
        const float* Af = (const float*)Ain;
        float4 a = *(const float4*)(Af + (size_t)row * D_MODEL + t * 4);
        a0 = a.x; a1 = a.y; a2 = a.z; a3 = a.w;
    }
    uint2 rp = *(const uint2*)(R + (size_t)row * D_MODEL + t * 4);
    float2 r0 = __half22float2(*(__half2*)&rp.x);
    float2 r1 = __half22float2(*(__half2*)&rp.y);
    float x0 = a0 + r0.x, x1 = a1 + r0.y, x2 = a2 + r1.x, x3 = a3 + r1.y;

    float sum = x0 + x1 + x2 + x3;
    float sq  = x0 * x0 + x1 * x1 + x2 * x2 + x3 * x3;

#pragma unroll
    for (int w = 16; w >= 1; w >>= 1) {
        sum += __shfl_xor_sync(0xffffffffu, sum, w);
        sq  += __shfl_xor_sync(0xffffffffu, sq, w);
    }
    __shared__ float ssum[8], ssq[8];
    __shared__ float s_mu, s_rstd;
    if ((t & 31) == 0) {
        ssum[t >> 5] = sum;
        ssq[t >> 5]  = sq;
    }
    __syncthreads();
    if (t == 0) {
        float S = 0.0f, Q = 0.0f;
#pragma unroll
        for (int i = 0; i < 8; i++) { S += ssum[i]; Q += ssq[i]; }
        float mu  = S * (1.0f / D_MODEL);
        float var = Q * (1.0f / D_MODEL) - mu * mu;
        s_mu   = mu;
        s_rstd = rsqrtf(var + 1e-5f);
    }
    __syncthreads();
    float mu = s_mu, rstd = s_rstd;

    float4 gg = *(const float4*)(g + t * 4);
    float4 bb = *(const float4*)(beta + t * 4);
    float4 ov;
    ov.x = (x0 - mu) * rstd * gg.x + bb.x;
    ov.y = (x1 - mu) * rstd * gg.y + bb.y;
    ov.z = (x2 - mu) * rstd * gg.z + bb.z;
    ov.w = (x3 - mu) * rstd * gg.w + bb.w;
    if (out)
        *(float4*)(out + (size_t)row * D_MODEL + t * 4) = ov;
    if (out_h) {
        __half2 h0 = __floats2half2_rn(ov.x, ov.y);
        __half2 h1 = __floats2half2_rn(ov.z, ov.w);
        uint2 pk;
        pk.x = *(uint32_t*)&h0;
        pk.y = *(uint32_t*)&h1;
        *(uint2*)(out_h + (size_t)row * D_MODEL + t * 4) = pk;
    }
}

// ---------------------------------------------------------------------------
extern "C" void kernel_launch(void* const* d_in, const int* in_sizes, int n_in,
                              void* d_out, int out_size)
{
    (void)in_sizes; (void)n_in; (void)out_size;

    const float* x     = (const float*)d_in[0];
    const float* w_q   = (const float*)d_in[1];
    const float* b_q   = (const float*)d_in[2];
    const float* w_k   = (const float*)d_in[3];
    const float* b_k   = (const float*)d_in[4];
    const float* w_v   = (const float*)d_in[5];
    const float* b_v   = (const float*)d_in[6];
    const float* w_o   = (const float*)d_in[7];
    const float* b_o   = (const float*)d_in[8];
    const float* w_ff1 = (const float*)d_in[9];
    const float* b_ff1 = (const float*)d_in[10];
    const float* w_ff2 = (const float*)d_in[11];
    const float* b_ff2 = (const float*)d_in[12];
    const float* ln1_g = (const float*)d_in[13];
    const float* ln1_b = (const float*)d_in[14];
    const float* ln2_g = (const float*)d_in[15];
    const float* ln2_b = (const float*)d_in[16];
    float* out = (float*)d_out;

    __half *qh, *kh, *vh, *ctxh, *t1h, *hh, *ffh;
    __half *xh, *wqh, *wkh, *wvh, *woh, *ff1h, *ff2h;
    cudaGetSymbolAddress((void**)&qh,   g_qh);
    cudaGetSymbolAddress((void**)&kh,   g_kh);
    cudaGetSymbolAddress((void**)&vh,   g_vh);
    cudaGetSymbolAddress((void**)&ctxh, g_ctxh);
    cudaGetSymbolAddress((void**)&t1h,  g_t1h);
    cudaGetSymbolAddress((void**)&hh,   g_hh);
    cudaGetSymbolAddress((void**)&ffh,  g_ffh);
    cudaGetSymbolAddress((void**)&xh,   g_xh);
    cudaGetSymbolAddress((void**)&wqh,  g_wqh);
    cudaGetSymbolAddress((void**)&wkh,  g_wkh);
    cudaGetSymbolAddress((void**)&wvh,  g_wvh);
    cudaGetSymbolAddress((void**)&woh,  g_woh);
    cudaGetSymbolAddress((void**)&ff1h, g_ff1h);
    cudaGetSymbolAddress((void**)&ff2h, g_ff2h);

    cudaFuncSetAttribute(attention_h_kernel,
                         cudaFuncAttributeMaxDynamicSharedMemorySize, ATT_SMEM);
    cudaFuncSetAttribute(qkv_h_kernel,
                         cudaFuncAttributeMaxDynamicSharedMemorySize, G_SMEM);
    cudaFuncSetAttribute(gemm_h_kernel<false>,
                         cudaFuncAttributeMaxDynamicSharedMemorySize, G_SMEM);
    cudaFuncSetAttribute(gemm_h_kernel<true>,
                         cudaFuncAttributeMaxDynamicSharedMemorySize, G_SMEM);

    dim3 gblk(G_THREADS);

    // 1) fp32 -> fp16 prepass (single launch, 2 float4 per thread)
    conv_all_kernel<<<(R_THREADS + 255) / 256, 256>>>(
        (const float4*)x, xh,
        (const float4*)w_q, wqh,
        (const float4*)w_k, wkh,
        (const float4*)w_v, wvh,
        (const float4*)w_o, woh,
        (const float4*)w_ff1, ff1h,
        (const float4*)w_ff2, ff2h);

    // 2) QKV projections (fused, grid.z = 3; q pre-scaled by QSCALE)
    qkv_h_kernel<<<dim3(D_MODEL / 128, NTOK / 128, 3), gblk, G_SMEM>>>(
        xh, wqh, b_q, wkh, b_k, wvh, b_v, qh, kh, vh, D_MODEL, D_MODEL);

    // 3) flash attention (KV tile 128) -> ctx (half)
    attention_h_kernel<<<dim3(SEQ / 128, BATCH * NHEAD), 256, ATT_SMEM>>>(
        qh, kh, vh, ctxh);

    // 4) output projection -> t1h (half)
    gemm_h_kernel<false><<<dim3(D_MODEL / 128, NTOK / 128), gblk, G_SMEM>>>(
        ctxh, woh, b_o, t1h, D_MODEL, D_MODEL);

    // 5) AddNorm1: hh = LN(x + t1h)  (half output only)
    add_ln_kernel<false><<<NTOK, 256>>>(x, t1h, ln1_g, ln1_b, nullptr, hh);

    // 6) FFN1 (ReLU) -> ffh (half)
    gemm_h_kernel<true><<<dim3(D_FF / 128, NTOK / 128), gblk, G_SMEM>>>(
        hh, ff1h, b_ff1, ffh, D_MODEL, D_FF);

    // 7) FFN2 -> t1h (half)
    gemm_h_kernel<false><<<dim3(D_MODEL / 128, NTOK / 128), gblk, G_SMEM>>>(
        ffh, ff2h, b_ff2, t1h, D_FF, D_MODEL);

    // 8) AddNorm2: out = LN(hh + t1h)
    add_ln_kernel<true><<<NTOK, 256>>>(hh, t1h, ln2_g, ln2_b, out, nullptr);
}

// round 14
// speedup vs baseline: 1.0522x; 1.0522x over previous
#include <cuda_runtime.h>
#include <cuda_fp16.h>
#include <math.h>
#include <stdint.h>

#define D_MODEL 1024
#define D_FF    4096
#define SEQ     2048
#define BATCH   2
#define NTOK    (BATCH*SEQ)   // 4096
#define NHEAD   16
#define HDIM    64

// ---------------- scratch (device globals; no allocation allowed) ----------
__device__ __half g_qh  [NTOK * D_MODEL];
__device__ __half g_kh  [NTOK * D_MODEL];
__device__ __half g_vh  [NTOK * D_MODEL];
__device__ __half g_ctxh[NTOK * D_MODEL];
__device__ __half g_t1h [NTOK * D_MODEL];
__device__ __half g_hh  [NTOK * D_MODEL];
__device__ __half g_ffh [NTOK * D_FF];
// half copies of inputs/weights
__device__ __half g_xh  [NTOK * D_MODEL];
__device__ __half g_wqh [D_MODEL * D_MODEL];
__device__ __half g_wkh [D_MODEL * D_MODEL];
__device__ __half g_wvh [D_MODEL * D_MODEL];
__device__ __half g_woh [D_MODEL * D_MODEL];
__device__ __half g_ff1h[D_MODEL * D_FF];
__device__ __half g_ff2h[D_FF * D_MODEL];

// ---------------------------------------------------------------------------
__device__ __forceinline__ void cp_async16(void* smem_dst, const void* gmem_src) {
    uint32_t da = (uint32_t)__cvta_generic_to_shared(smem_dst);
    asm volatile("cp.async.cg.shared.global [%0], [%1], 16;\n" :: "r"(da), "l"(gmem_src));
}
__device__ __forceinline__ void cp_commit() {
    asm volatile("cp.async.commit_group;\n");
}
__device__ __forceinline__ void cp_wait1() {
    asm volatile("cp.async.wait_group 1;\n");
}
__device__ __forceinline__ void mma_f16(float* c, const uint32_t* a,
                                        uint32_t b0, uint32_t b1) {
    asm volatile(
        "mma.sync.aligned.m16n8k16.row.col.f32.f16.f16.f32 "
        "{%0,%1,%2,%3}, {%4,%5,%6,%7}, {%8,%9}, {%0,%1,%2,%3};"
        : "+f"(c[0]), "+f"(c[1]), "+f"(c[2]), "+f"(c[3])
        : "r"(a[0]), "r"(a[1]), "r"(a[2]), "r"(a[3]), "r"(b0), "r"(b1));
}
#define LDSM_X4(r0, r1, r2, r3, addr) \
    asm volatile("ldmatrix.sync.aligned.m8n8.x4.shared.b16 {%0,%1,%2,%3}, [%4];" \
        : "=r"(r0), "=r"(r1), "=r"(r2), "=r"(r3) : "r"(addr))
#define LDSM_X4T(r0, r1, r2, r3, addr) \
    asm volatile("ldmatrix.sync.aligned.m8n8.x4.trans.shared.b16 {%0,%1,%2,%3}, [%4];" \
        : "=r"(r0), "=r"(r1), "=r"(r2), "=r"(r3) : "r"(addr))

// fast exp2 on the FMA pipe (x <= 0), rel err ~2e-6
__device__ __forceinline__ float exp2p(float x) {
    x = fmaxf(x, -126.0f);
    float z = x + 12582912.0f;
    float f = x - (z - 12582912.0f);
    float p =            1.3333558146e-3f;
    p = fmaf(p, f, 9.6181291918e-3f);
    p = fmaf(p, f, 5.5504108664e-2f);
    p = fmaf(p, f, 2.4022650695e-1f);
    p = fmaf(p, f, 6.9314718056e-1f);
    p = fmaf(p, f, 1.0f);
    return __int_as_float((__float_as_int(z) << 23) + __float_as_int(p));
}

// ===========================================================================
// Prepass: convert x + 6 weight tensors fp32 -> fp16, 2 float4 per thread.
// ===========================================================================
#define R_N0 (NTOK * D_MODEL / 4)
#define R_N1 (D_MODEL * D_MODEL / 4)
#define R_N2 (D_MODEL * D_FF / 4)
#define R_TOTAL (R_N0 + 4 * R_N1 + 2 * R_N2)
#define R_THREADS ((R_TOTAL + 1) / 2)

__device__ __forceinline__ void conv_map(int i, const float4* x, __half* xh,
    const float4* wq, __half* wqh, const float4* wk, __half* wkh,
    const float4* wv, __half* wvh, const float4* wo, __half* woh,
    const float4* f1, __half* f1h, const float4* f2, __half* f2h,
    const float4*& s, __half*& d, int& j)
{
    int off;
    if      (i < R_N0)                 { s = x;  d = xh;  off = 0; }
    else if (i < R_N0 + R_N1)          { s = wq; d = wqh; off = R_N0; }
    else if (i < R_N0 + 2*R_N1)        { s = wk; d = wkh; off = R_N0 + R_N1; }
    else if (i < R_N0 + 3*R_N1)        { s = wv; d = wvh; off = R_N0 + 2*R_N1; }
    else if (i < R_N0 + 4*R_N1)        { s = wo; d = woh; off = R_N0 + 3*R_N1; }
    else if (i < R_N0 + 4*R_N1 + R_N2) { s = f1; d = f1h; off = R_N0 + 4*R_N1; }
    else                               { s = f2; d = f2h; off = R_N0 + 4*R_N1 + R_N2; }
    j = i - off;
}

__global__ void __launch_bounds__(256) conv_all_kernel(
    const float4* __restrict__ x,   __half* __restrict__ xh,
    const float4* __restrict__ wq,  __half* __restrict__ wqh,
    const float4* __restrict__ wk,  __half* __restrict__ wkh,
    const float4* __restrict__ wv,  __half* __restrict__ wvh,
    const float4* __restrict__ wo,  __half* __restrict__ woh,
    const float4* __restrict__ f1,  __half* __restrict__ f1h,
    const float4* __restrict__ f2,  __half* __restrict__ f2h)
{
    int t = blockIdx.x * 256 + threadIdx.x;
    int i0 = t;
    int i1 = t + R_THREADS;

    const float4 *s0 = nullptr, *s1 = nullptr;
    __half *d0 = nullptr, *d1 = nullptr;
    int j0 = 0, j1 = 0;
    bool v0 = (i0 < R_TOTAL), v1 = (i1 < R_TOTAL);
    if (v0) conv_map(i0, x, xh, wq, wqh, wk, wkh, wv, wvh, wo, woh, f1, f1h, f2, f2h, s0, d0, j0);
    if (v1) conv_map(i1, x, xh, wq, wqh, wk, wkh, wv, wvh, wo, woh, f1, f1h, f2, f2h, s1, d1, j1);

    float4 a, b;
    if (v0) a = s0[j0];
    if (v1) b = s1[j1];

    if (v0) {
        __half2 h0 = __floats2half2_rn(a.x, a.y);
        __half2 h1 = __floats2half2_rn(a.z, a.w);
        uint2 pk;
        pk.x = *(uint32_t*)&h0;
        pk.y = *(uint32_t*)&h1;
        *(uint2*)(d0 + (size_t)j0 * 4) = pk;
    }
    if (v1) {
        __half2 h0 = __floats2half2_rn(b.x, b.y);
        __half2 h1 = __floats2half2_rn(b.z, b.w);
        uint2 pk;
        pk.x = *(uint32_t*)&h0;
        pk.y = *(uint32_t*)&h1;
        *(uint2*)(d1 + (size_t)j1 * 4) = pk;
    }
}

// ===========================================================================
// fp16 tensor-core GEMM (R8 config — mainloop byte-identical).
// CTA 128x128, BK=64, 3-stage cp.async, 4 warps (2x2), warp tile 64x64.
// ===========================================================================
#define GA_BYTES 16384
#define GB_PITCH 272
#define GB_BYTES (64 * GB_PITCH)
#define G_STAGE  (GA_BYTES + GB_BYTES)
#define G_SMEM   (3 * G_STAGE)
#define G_THREADS 128

template <bool RELU>
__device__ __forceinline__ void gemm_h_body(
    const __half* __restrict__ A, const __half* __restrict__ W,
    const float* __restrict__ bias, __half* __restrict__ Cout,
    int K, int M, int row0, int col0, float oscale)
{
    extern __shared__ char smem[];
    const int tid  = threadIdx.x;
    const int lane = tid & 31;
    const int wid  = tid >> 5;
    const int warp_m = wid & 1;
    const int warp_n = wid >> 1;
    const uint32_t sbase = (uint32_t)__cvta_generic_to_shared(smem);

    float acc[4][8][4];
#pragma unroll
    for (int mt = 0; mt < 4; mt++)
#pragma unroll
        for (int nt = 0; nt < 8; nt++)
#pragma unroll
            for (int r = 0; r < 4; r++) acc[mt][nt][r] = 0.0f;

    const int KT = K / 64;

    auto load_stage = [&](int kt) {
        char* base = smem + (kt % 3) * G_STAGE;
        const int k0 = kt * 64;
#pragma unroll
        for (int i = 0; i < 8; i++) {
            int c = tid + G_THREADS * i;
            int r = c >> 3, u = c & 7;
            cp_async16(base + r * 128 + (((u ^ (r & 7))) << 4),
                       A + (size_t)(row0 + r) * K + k0 + u * 8);
        }
#pragma unroll
        for (int i = 0; i < 8; i++) {
            int c = tid + G_THREADS * i;
            int k = c >> 4, u = c & 15;
            cp_async16(base + GA_BYTES + k * GB_PITCH + u * 16,
                       W + (size_t)(k0 + k) * M + col0 + u * 8);
        }
        cp_commit();
    };

    load_stage(0);
    load_stage(1);

    for (int kt = 0; kt < KT; kt++) {
        cp_wait1();
        __syncthreads();
        if (kt + 2 < KT) load_stage(kt + 2);
        else cp_commit();

        const uint32_t ab = sbase + (uint32_t)((kt % 3) * G_STAGE);
        const uint32_t bb = ab + GA_BYTES;

#pragma unroll
        for (int k16 = 0; k16 < 4; k16++) {
            uint32_t a[4][4];
#pragma unroll
            for (int mt = 0; mt < 4; mt++) {
                int m = warp_m * 64 + mt * 16 + (lane & 7) + ((lane >> 3) & 1) * 8;
                int u = k16 * 2 + (lane >> 4);
                LDSM_X4(a[mt][0], a[mt][1], a[mt][2], a[mt][3],
                        ab + m * 128 + ((u ^ (m & 7)) << 4));
            }
            uint32_t b[8][2];
#pragma unroll
            for (int ng = 0; ng < 4; ng++) {
                int k    = k16 * 16 + (lane & 7) + ((lane >> 3) & 1) * 8;
                int noff = warp_n * 64 + ng * 16 + ((lane >> 4) & 1) * 8;
                LDSM_X4T(b[ng*2][0], b[ng*2][1], b[ng*2+1][0], b[ng*2+1][1],
                         bb + k * GB_PITCH + noff * 2);
            }
#pragma unroll
            for (int mt = 0; mt < 4; mt++)
#pragma unroll
                for (int nt = 0; nt < 8; nt++)
                    mma_f16(acc[mt][nt], a[mt], b[nt][0], b[nt][1]);
        }
        __syncthreads();
    }

    // ---- epilogue: bias (+ReLU), half2 stores ----
#pragma unroll
    for (int nt = 0; nt < 8; nt++) {
        int ncol = col0 + warp_n * 64 + nt * 8 + (lane & 3) * 2;
        float bj0 = bias[ncol];
        float bj1 = bias[ncol + 1];
#pragma unroll
        for (int mt = 0; mt < 4; mt++) {
            int r0 = row0 + warp_m * 64 + mt * 16 + (lane >> 2);
            float v0 = (acc[mt][nt][0] + bj0) * oscale;
            float v1 = (acc[mt][nt][1] + bj1) * oscale;
            float v2 = (acc[mt][nt][2] + bj0) * oscale;
            float v3 = (acc[mt][nt][3] + bj1) * oscale;
            if (RELU) {
                v0 = fmaxf(v0, 0.0f); v1 = fmaxf(v1, 0.0f);
                v2 = fmaxf(v2, 0.0f); v3 = fmaxf(v3, 0.0f);
            }
            __half2 h0 = __floats2half2_rn(v0, v1);
            __half2 h1 = __floats2half2_rn(v2, v3);
            *(__half2*)(Cout + (size_t)r0 * M + ncol)       = h0;
            *(__half2*)(Cout + (size_t)(r0 + 8) * M + ncol) = h1;
        }
    }
}

template <bool RELU>
__global__ void __launch_bounds__(G_THREADS) gemm_h_kernel(
    const __half* __restrict__ A, const __half* __restrict__ W,
    const float* __restrict__ bias, __half* __restrict__ Cout, int K, int M)
{
    gemm_h_body<RELU>(A, W, bias, Cout, K, M,
                      blockIdx.y * 128, blockIdx.x * 128, 1.0f);
}

#define QSCALE (0.125f * 1.4426950408889634f)   // 1/sqrt(64) * log2(e)

__global__ void __launch_bounds__(G_THREADS) qkv_h_kernel(
    const __half* __restrict__ x,
    const __half* __restrict__ wq, const float* __restrict__ bq,
    const __half* __restrict__ wk, const float* __restrict__ bk,
    const __half* __restrict__ wv, const float* __restrict__ bv,
    __half* __restrict__ q, __half* __restrict__ k, __half* __restrict__ v,
    int K, int M)
{
    const int z = blockIdx.z;
    const __half* W    = (z == 0) ? wq : (z == 1) ? wk : wv;
    const float*  bias = (z == 0) ? bq : (z == 1) ? bk : bv;
    __half*       C    = (z == 0) ? q  : (z == 1) ? k  : v;
    float oscale = (z == 0) ? QSCALE : 1.0f;
    gemm_h_body<false>(x, W, bias, C, K, M,
                       blockIdx.y * 128, blockIdx.x * 128, oscale);
}

// ===========================================================================
// Flash attention, fp16 mma (f32 acc), KV tile = 128.
// P fragments built DIRECTLY in registers from S accumulators (the mma C
// layout == mma A layout for the same thread): no P smem, no ldmatrix,
// no syncwarp between S and PV phases.
// ===========================================================================
#define AK_PITCH 144
#define AK_BYTES (128 * AK_PITCH)
#define AV_OFF   (2 * AK_BYTES)
#define ATT_SMEM (4 * AK_BYTES)      // K x2 + V x2 stages only (73728 B)

__global__ void __launch_bounds__(256, 1) attention_h_kernel(
    const __half* __restrict__ Q, const __half* __restrict__ K,
    const __half* __restrict__ V, __half* __restrict__ O)
{
    extern __shared__ char smem[];
    const uint32_t sbase = (uint32_t)__cvta_generic_to_shared(smem);

    const int tid  = threadIdx.x;
    const int lane = tid & 31;
    const int wid  = tid >> 5;
    const int b    = blockIdx.y >> 4;
    const int h    = blockIdx.y & 15;
    const int qr   = blockIdx.x * 128 + wid * 16;

    const __half* Qb = Q + ((size_t)(b * SEQ + qr)) * D_MODEL + h * HDIM;
    const __half* Kb = K + ((size_t)(b * SEQ)) * D_MODEL + h * HDIM;
    const __half* Vb = V + ((size_t)(b * SEQ)) * D_MODEL + h * HDIM;

    uint32_t qf[4][4];
    {
        const int r = lane >> 2, c2 = (lane & 3) * 2;
#pragma unroll
        for (int k16 = 0; k16 < 4; k16++) {
            qf[k16][0] = *(const uint32_t*)(Qb + (size_t)r * D_MODEL + k16 * 16 + c2);
            qf[k16][1] = *(const uint32_t*)(Qb + (size_t)(r + 8) * D_MODEL + k16 * 16 + c2);
            qf[k16][2] = *(const uint32_t*)(Qb + (size_t)r * D_MODEL + k16 * 16 + c2 + 8);
            qf[k16][3] = *(const uint32_t*)(Qb + (size_t)(r + 8) * D_MODEL + k16 * 16 + c2 + 8);
        }
    }

    auto load_kv = [&](int kt, int st) {
        const __half* Kt = Kb + (size_t)kt * 128 * D_MODEL;
        const __half* Vt = Vb + (size_t)kt * 128 * D_MODEL;
        char* kd = smem + st * AK_BYTES;
        char* vd = smem + AV_OFF + st * AK_BYTES;
#pragma unroll
        for (int i = 0; i < 4; i++) {
            int c = tid + 256 * i;
            int r = c >> 3, u = c & 7;
            cp_async16(kd + r * AK_PITCH + u * 16, Kt + (size_t)r * D_MODEL + u * 8);
            cp_async16(vd + r * AK_PITCH + u * 16, Vt + (size_t)r * D_MODEL + u * 8);
        }
        cp_commit();
    };

    float m0 = -1e30f, m1 = -1e30f, l0 = 0.0f, l1 = 0.0f;
    float oacc[8][4];
#pragma unroll
    for (int dt = 0; dt < 8; dt++)
#pragma unroll
        for (int r = 0; r < 4; r++) oacc[dt][r] = 0.0f;

    load_kv(0, 0);
    load_kv(1, 1);
    cp_wait1();
    __syncthreads();

    const int NKT = SEQ / 128;   // 16
    for (int kt = 0; kt < NKT; kt++) {
        const __half* kd = (const __half*)(smem + (kt & 1) * AK_BYTES);
        const uint32_t vdb = sbase + (uint32_t)(AV_OFF + (kt & 1) * AK_BYTES);

        // ---- S = Q @ K^T over 128 KV rows (16 n-tiles) ----
        float sacc[16][4];
#pragma unroll
        for (int nt = 0; nt < 16; nt++) {
            sacc[nt][0] = 0.0f; sacc[nt][1] = 0.0f;
            sacc[nt][2] = 0.0f; sacc[nt][3] = 0.0f;
            const int j = nt * 8 + (lane >> 2);
#pragma unroll
            for (int k16 = 0; k16 < 4; k16++) {
                int idx = j * 72 + k16 * 16 + (lane & 3) * 2;
                uint32_t b0 = *(const uint32_t*)(kd + idx);
                uint32_t b1 = *(const uint32_t*)(kd + idx + 8);
                mma_f16(sacc[nt], qf[k16], b0, b1);
            }
        }

        // ---- softmax round (base 2) ----
        float mx0 = -1e30f, mx1 = -1e30f;
#pragma unroll
        for (int nt = 0; nt < 16; nt++) {
            mx0 = fmaxf(mx0, fmaxf(sacc[nt][0], sacc[nt][1]));
            mx1 = fmaxf(mx1, fmaxf(sacc[nt][2], sacc[nt][3]));
        }
        mx0 = fmaxf(mx0, __shfl_xor_sync(0xffffffffu, mx0, 1));
        mx0 = fmaxf(mx0, __shfl_xor_sync(0xffffffffu, mx0, 2));
        mx1 = fmaxf(mx1, __shfl_xor_sync(0xffffffffu, mx1, 1));
        mx1 = fmaxf(mx1, __shfl_xor_sync(0xffffffffu, mx1, 2));
        float mn0 = fmaxf(m0, mx0), mn1 = fmaxf(m1, mx1);
        float sc0 = exp2p(m0 - mn0), sc1 = exp2p(m1 - mn1);
        m0 = mn0; m1 = mn1;

        // ---- exp + pack P fragments directly in registers ----
        // S-mma C layout == PV-mma A layout per thread:
        //   pfr[k16][0] = (r,   j=16k16+2c..+1) = exp(sacc[2k16][0..1])
        //   pfr[k16][1] = (r+8, same)           = exp(sacc[2k16][2..3])
        //   pfr[k16][2] = (r,   j=16k16+8+2c..) = exp(sacc[2k16+1][0..1])
        //   pfr[k16][3] = (r+8, same)           = exp(sacc[2k16+1][2..3])
        uint32_t pfr[8][4];
        float rs0 = 0.0f, rs1 = 0.0f;
#pragma unroll
        for (int nt = 0; nt < 16; nt++) {
            float p0 = exp2p(sacc[nt][0] - mn0);
            float p1 = exp2p(sacc[nt][1] - mn0);
            float p2 = exp2p(sacc[nt][2] - mn1);
            float p3 = exp2p(sacc[nt][3] - mn1);
            rs0 += p0 + p1;
            rs1 += p2 + p3;
            __half2 h01 = __floats2half2_rn(p0, p1);
            __half2 h23 = __floats2half2_rn(p2, p3);
            pfr[nt >> 1][(nt & 1) * 2 + 0] = *(uint32_t*)&h01;
            pfr[nt >> 1][(nt & 1) * 2 + 1] = *(uint32_t*)&h23;
        }
        rs0 += __shfl_xor_sync(0xffffffffu, rs0, 1);
        rs0 += __shfl_xor_sync(0xffffffffu, rs0, 2);
        rs1 += __shfl_xor_sync(0xffffffffu, rs1, 1);
        rs1 += __shfl_xor_sync(0xffffffffu, rs1, 2);
        l0 = l0 * sc0 + rs0;
        l1 = l1 * sc1 + rs1;
#pragma unroll
        for (int dt = 0; dt < 8; dt++) {
            oacc[dt][0] *= sc0; oacc[dt][1] *= sc0;
            oacc[dt][2] *= sc1; oacc[dt][3] *= sc1;
        }

        // ---- O += P @ V  (128 j rows = 8 k16 blocks; P already in regs) ----
#pragma unroll
        for (int k16 = 0; k16 < 8; k16++) {
            uint32_t vb[8][2];
#pragma unroll
            for (int ng = 0; ng < 4; ng++) {
                int j    = k16 * 16 + (lane & 7) + ((lane >> 3) & 1) * 8;
                int doff = ng * 16 + ((lane >> 4) & 1) * 8;
                LDSM_X4T(vb[ng*2][0], vb[ng*2][1], vb[ng*2+1][0], vb[ng*2+1][1],
                         vdb + j * AK_PITCH + doff * 2);
            }
#pragma unroll
            for (int dt = 0; dt < 8; dt++)
                mma_f16(oacc[dt], pfr[k16], vb[dt][0], vb[dt][1]);
        }

        __syncthreads();
        if (kt + 2 < NKT) load_kv(kt + 2, kt & 1);
        else cp_commit();
        cp_wait1();
        __syncthreads();
    }

    float inv0 = 1.0f / l0, inv1 = 1.0f / l1;
    const size_t row0 = (size_t)(b * SEQ + qr + (lane >> 2));
#pragma unroll
    for (int dt = 0; dt < 8; dt++) {
        int col = h * HDIM + dt * 8 + 2 * (lane & 3);
        __half2 h0 = __floats2half2_rn(oacc[dt][0] * inv0, oacc[dt][1] * inv0);
        __half2 h1 = __floats2half2_rn(oacc[dt][2] * inv1, oacc[dt][3] * inv1);
        *(__half2*)(O + row0 * D_MODEL + col)       = h0;
        *(__half2*)(O + (row0 + 8) * D_MODEL + col) = h1;
    }
}

// ---------------------------------------------------------------------------
// Fused residual add + LayerNorm. A: fp32 (x) or half (hh). R: half (t1h).
// ---------------------------------------------------------------------------
template <bool AHALF>
__global__ void __launch_bounds__(256) add_ln_kernel(
    const void* __restrict__ Ain, const __half* __restrict__ R,
    const float* __restrict__ g, const float* __restrict__ beta,
    float* __restrict__ out, __half* __restrict__ out_h)
{
    const int row = blockIdx.x;
    const int t   = threadIdx.x;

    float a0, a1, a2, a3;
    if (AHALF) {
        const __half* Ah = (const __half*)Ain;
        uint2 pk = *(const uint2*)(Ah + (size_t)row * D_MODEL + t * 4);
        float2 f0 = __half22float2(*(__half2*)&pk.x);
        float2 f1 = __half22float2(*(__half2*)&pk.y);
        a0 = f0.x; a1 = f0.y; a2 = f1.x; a3 = f1.y;
    } else {
        const float* Af = (const float*)Ain;
        float4 a = *(const float4*)(Af + (size_t)row * D_MODEL + t * 4);
        a0 = a.x; a1 = a.y; a2 = a.z; a3 = a.w;
    }
    uint2 rp = *(const uint2*)(R + (size_t)row * D_MODEL + t * 4);
    float2 r0 = __half22float2(*(__half2*)&rp.x);
    float2 r1 = __half22float2(*(__half2*)&rp.y);
    float x0 = a0 + r0.x, x1 = a1 + r0.y, x2 = a2 + r1.x, x3 = a3 + r1.y;

    float sum = x0 + x1 + x2 + x3;
    float sq  = x0 * x0 + x1 * x1 + x2 * x2 + x3 * x3;

#pragma unroll
    for (int w = 16; w >= 1; w >>= 1) {
        sum += __shfl_xor_sync(0xffffffffu, sum, w);
        sq  += __shfl_xor_sync(0xffffffffu, sq, w);
    }
    __shared__ float ssum[8], ssq[8];
    __shared__ float s_mu, s_rstd;
    if ((t & 31) == 0) {
        ssum[t >> 5] = sum;
        ssq[t >> 5]  = sq;
    }
    __syncthreads();
    if (t == 0) {
        float S = 0.0f, Q = 0.0f;
#pragma unroll
        for (int i = 0; i < 8; i++) { S += ssum[i]; Q += ssq[i]; }
        float mu  = S * (1.0f / D_MODEL);
        float var = Q * (1.0f / D_MODEL) - mu * mu;
        s_mu   = mu;
        s_rstd = rsqrtf(var + 1e-5f);
    }
    __syncthreads();
    float mu = s_mu, rstd = s_rstd;

    float4 gg = *(const float4*)(g + t * 4);
    float4 bb = *(const float4*)(beta + t * 4);
    float4 ov;
    ov.x = (x0 - mu) * rstd * gg.x + bb.x;
    ov.y = (x1 - mu) * rstd * gg.y + bb.y;
    ov.z = (x2 - mu) * rstd * gg.z + bb.z;
    ov.w = (x3 - mu) * rstd * gg.w + bb.w;
    if (out)
        *(float4*)(out + (size_t)row * D_MODEL + t * 4) = ov;
    if (out_h) {
        __half2 h0 = __floats2half2_rn(ov.x, ov.y);
        __half2 h1 = __floats2half2_rn(ov.z, ov.w);
        uint2 pk;
        pk.x = *(uint32_t*)&h0;
        pk.y = *(uint32_t*)&h1;
        *(uint2*)(out_h + (size_t)row * D_MODEL + t * 4) = pk;
    }
}

// ---------------------------------------------------------------------------
extern "C" void kernel_launch(void* const* d_in, const int* in_sizes, int n_in,
                              void* d_out, int out_size)
{
    (void)in_sizes; (void)n_in; (void)out_size;

    const float* x     = (const float*)d_in[0];
    const float* w_q   = (const float*)d_in[1];
    const float* b_q   = (const float*)d_in[2];
    const float* w_k   = (const float*)d_in[3];
    const float* b_k   = (const float*)d_in[4];
    const float* w_v   = (const float*)d_in[5];
    const float* b_v   = (const float*)d_in[6];
    const float* w_o   = (const float*)d_in[7];
    const float* b_o   = (const float*)d_in[8];
    const float* w_ff1 = (const float*)d_in[9];
    const float* b_ff1 = (const float*)d_in[10];
    const float* w_ff2 = (const float*)d_in[11];
    const float* b_ff2 = (const float*)d_in[12];
    const float* ln1_g = (const float*)d_in[13];
    const float* ln1_b = (const float*)d_in[14];
    const float* ln2_g = (const float*)d_in[15];
    const float* ln2_b = (const float*)d_in[16];
    float* out = (float*)d_out;

    __half *qh, *kh, *vh, *ctxh, *t1h, *hh, *ffh;
    __half *xh, *wqh, *wkh, *wvh, *woh, *ff1h, *ff2h;
    cudaGetSymbolAddress((void**)&qh,   g_qh);
    cudaGetSymbolAddress((void**)&kh,   g_kh);
    cudaGetSymbolAddress((void**)&vh,   g_vh);
    cudaGetSymbolAddress((void**)&ctxh, g_ctxh);
    cudaGetSymbolAddress((void**)&t1h,  g_t1h);
    cudaGetSymbolAddress((void**)&hh,   g_hh);
    cudaGetSymbolAddress((void**)&ffh,  g_ffh);
    cudaGetSymbolAddress((void**)&xh,   g_xh);
    cudaGetSymbolAddress((void**)&wqh,  g_wqh);
    cudaGetSymbolAddress((void**)&wkh,  g_wkh);
    cudaGetSymbolAddress((void**)&wvh,  g_wvh);
    cudaGetSymbolAddress((void**)&woh,  g_woh);
    cudaGetSymbolAddress((void**)&ff1h, g_ff1h);
    cudaGetSymbolAddress((void**)&ff2h, g_ff2h);

    cudaFuncSetAttribute(attention_h_kernel,
                         cudaFuncAttributeMaxDynamicSharedMemorySize, ATT_SMEM);
    cudaFuncSetAttribute(qkv_h_kernel,
                         cudaFuncAttributeMaxDynamicSharedMemorySize, G_SMEM);
    cudaFuncSetAttribute(gemm_h_kernel<false>,
                         cudaFuncAttributeMaxDynamicSharedMemorySize, G_SMEM);
    cudaFuncSetAttribute(gemm_h_kernel<true>,
                         cudaFuncAttributeMaxDynamicSharedMemorySize, G_SMEM);

    dim3 gblk(G_THREADS);

    // 1) fp32 -> fp16 prepass
    conv_all_kernel<<<(R_THREADS + 255) / 256, 256>>>(
        (const float4*)x, xh,
        (const float4*)w_q, wqh,
        (const float4*)w_k, wkh,
        (const float4*)w_v, wvh,
        (const float4*)w_o, woh,
        (const float4*)w_ff1, ff1h,
        (const float4*)w_ff2, ff2h);

    // 2) QKV projections (fused, grid.z = 3; q pre-scaled by QSCALE)
    qkv_h_kernel<<<dim3(D_MODEL / 128, NTOK / 128, 3), gblk, G_SMEM>>>(
        xh, wqh, b_q, wkh, b_k, wvh, b_v, qh, kh, vh, D_MODEL, D_MODEL);

    // 3) flash attention (KV tile 128, register-resident P) -> ctx (half)
    attention_h_kernel<<<dim3(SEQ / 128, BATCH * NHEAD), 256, ATT_SMEM>>>(
        qh, kh, vh, ctxh);

    // 4) output projection -> t1h (half)
    gemm_h_kernel<false><<<dim3(D_MODEL / 128, NTOK / 128), gblk, G_SMEM>>>(
        ctxh, woh, b_o, t1h, D_MODEL, D_MODEL);

    // 5) AddNorm1: hh = LN(x + t1h)
    add_ln_kernel<false><<<NTOK, 256>>>(x, t1h, ln1_g, ln1_b, nullptr, hh);

    // 6) FFN1 (ReLU) -> ffh (half)
    gemm_h_kernel<true><<<dim3(D_FF / 128, NTOK / 128), gblk, G_SMEM>>>(
        hh, ff1h, b_ff1, ffh, D_MODEL, D_FF);

    // 7) FFN2 -> t1h (half)
    gemm_h_kernel<false><<<dim3(D_MODEL / 128, NTOK / 128), gblk, G_SMEM>>>(
        ffh, ff2h, b_ff2, t1h, D_FF, D_MODEL);

    // 8) AddNorm2: out = LN(hh + t1h)
    add_ln_kernel<true><<<NTOK, 256>>>(hh, t1h, ln2_g, ln2_b, out, nullptr);
}